// round 8
// baseline (speedup 1.0000x reference)
#include <cuda_runtime.h>
#include <cmath>
#include <cstdint>

#define D_MODEL 512
#define SEQ     1024
#define NB      8
#define NHEADS  8
#define DHEAD   64
#define FF      2048
#define NROWS   (NB*SEQ)    /* 8192 */
#define NDEPTH  3

// ---------------- scratch (device globals; no allocation allowed) ----------
__device__ float g_x   [NROWS * D_MODEL];
__device__ float g_h   [NROWS * D_MODEL];
__device__ float g_qkv [NROWS * 3 * D_MODEL];
__device__ float g_sim [67108864];                 // 64 * 1024 * 1024
__device__ float g_ao  [NROWS * D_MODEL];
__device__ float g_ffg [NROWS * FF];
__device__ float g_pool[NB * 8 * D_MODEL];
__device__ float g_wt  [12845056];                 // transposed weights
__device__ float g_vt  [NB * NHEADS * DHEAD * SEQ];// V^T per (b,h): [64][1024]

#define OFF_PROJ 0
#define OFF_QKV  262144
#define OFF_WOUT 2621440
#define OFF_W1   3407872
#define OFF_W2   9699328

// GEMM modes
#define M_PLAIN 0
#define M_GEGLU 1
#define M_SPMAX 2

// ---------------------------------------------------------------------------
__device__ __forceinline__ void cp16(uint32_t sa, const float* ga) {
    asm volatile("cp.async.cg.shared.global [%0], [%1], 16;" :: "r"(sa), "l"(ga) : "memory");
}
__device__ __forceinline__ uint32_t smem_u32(const void* p) {
    uint32_t a;
    asm("{ .reg .u64 t; cvta.to.shared.u64 t, %1; cvt.u32.u64 %0, t; }"
        : "=r"(a) : "l"(p));
    return a;
}
__device__ __forceinline__ void cp_commit() {
    asm volatile("cp.async.commit_group;" ::: "memory");
}
// bf16x3 MMA: m16n8k16, row.col, f32 accum
__device__ __forceinline__ void mma16(float* d, const uint32_t* a, const uint32_t* b) {
    asm volatile(
        "mma.sync.aligned.m16n8k16.row.col.f32.bf16.bf16.f32 "
        "{%0,%1,%2,%3}, {%4,%5,%6,%7}, {%8,%9}, {%0,%1,%2,%3};"
        : "+f"(d[0]), "+f"(d[1]), "+f"(d[2]), "+f"(d[3])
        : "r"(a[0]), "r"(a[1]), "r"(a[2]), "r"(a[3]), "r"(b[0]), "r"(b[1]));
}
// split float2 -> packed bf16 hi pair + packed bf16 lo pair
__device__ __forceinline__ void split2(float2 v, uint32_t& hi, uint32_t& lo) {
    asm("cvt.rn.bf16x2.f32 %0, %1, %2;" : "=r"(hi) : "f"(v.y), "f"(v.x));
    const float h0 = __uint_as_float(hi << 16);
    const float h1 = __uint_as_float(hi & 0xFFFF0000u);
    const float r0 = v.x - h0;
    const float r1 = v.y - h1;
    asm("cvt.rn.bf16x2.f32 %0, %1, %2;" : "=r"(lo) : "f"(r1), "f"(r0));
}

// ---------------------------------------------------------------------------
// bf16x3 mma.sync GEMM:  C[M,N] = alpha * A[M,K] @ Bt[N,K]^T (+bias+resid+pos)
// MODE == M_GEGLU: B cols interleaved (a0,g0,...); epilogue stores
//   (a+b_a)*gelu(g+b_g) at C[row, col/2], ldc = FF.
// MODE == M_SPMAX: A rows are sparsemax'ed on the fly: prologue computes
//   tau per row (bisection + exact refinement), mainloop applies
//   max(a - tau, 0) before the bf16 split. Requires grid.x == 1 (N == BN)
//   and K == SEQ so each block owns its 128 A rows exclusively.
// ---------------------------------------------------------------------------
template<int BN, int MODE>
__global__ void __launch_bounds__(256, 2)
mgemm_kernel(const float* __restrict__ A, long lda, long aO, long aI,
             const float* __restrict__ B, long ldb, long bO, long bI,
             float* __restrict__ C, long ldc, long cO, long cI,
             int K,
             const float* __restrict__ bias,
             const float* __restrict__ resid,
             const float* __restrict__ pos,
             float alpha)
{
    constexpr int BM = 128;
    constexpr int WN = BN / 2;       // warp tile: 32 x WN (4x2 warp grid)
    constexpr int NI = WN / 8;       // n-tiles per warp
    constexpr int PITCH = 40;        // floats per smem row (160B)
    constexpr int STAGE_F = (BM + BN) * PITCH;

    extern __shared__ float smem[];
    float* tau_s = smem + 2 * STAGE_F;   // [128] (SPMAX only)

    const int z = blockIdx.z, zo = z >> 3, zi = z & 7;
    A += zo * aO + zi * aI;
    B += zo * bO + zi * bI;
    C += zo * cO + zi * cI;
    const float* Rz = resid ? resid + zo * cO + zi * cI : nullptr;

    const long m0 = (long)blockIdx.y * BM;
    const long n0 = (long)blockIdx.x * BN;
    A += m0 * lda;
    B += n0 * ldb;

    const int t    = threadIdx.x;
    const int wid  = t >> 5, lane = t & 31;
    const int wr   = wid & 3, wc = wid >> 2;
    const int g    = lane >> 2, c = lane & 3;

    const uint32_t sbase = smem_u32(smem);
    const int niter = K >> 5;        // chunks of K=32

    auto load_stage = [&](int s, int kc) {
        const uint32_t sA = sbase + (uint32_t)(s * STAGE_F) * 4u;
        const uint32_t sB = sA + BM * PITCH * 4u;
        const float* ga = A + kc * 32;
        const float* gb = B + kc * 32;
        const int r0  = t >> 3;
        const int seg = (t & 7) * 16;
#pragma unroll
        for (int p = 0; p < BM / 32; ++p) {
            const int r = p * 32 + r0;
            cp16(sA + r * 160 + seg, ga + (long)r * lda + (t & 7) * 4);
        }
#pragma unroll
        for (int p = 0; p < BN / 32; ++p) {
            const int r = p * 32 + r0;
            cp16(sB + r * 160 + seg, gb + (long)r * ldb + (t & 7) * 4);
        }
        cp_commit();
    };

    load_stage(0, 0);

    // ---- SPMAX prologue: tau per A row (8 warps x 16 rows, regs + shfl) ----
    if (MODE == M_SPMAX) {
#pragma unroll 1
        for (int r = 0; r < 16; ++r) {
            const int row = wid * 16 + r;
            const float4* zr = (const float4*)(A + (long)row * lda);
            float4 zv[8];
#pragma unroll
            for (int j = 0; j < 8; ++j) zv[j] = zr[j * 32 + lane];

            float m = -1e30f;
#pragma unroll
            for (int j = 0; j < 8; ++j)
                m = fmaxf(m, fmaxf(fmaxf(zv[j].x, zv[j].y), fmaxf(zv[j].z, zv[j].w)));
#pragma unroll
            for (int off = 16; off; off >>= 1)
                m = fmaxf(m, __shfl_xor_sync(~0u, m, off));

            float lo = m - 1.f, hi = m;
#pragma unroll 1
            for (int it = 0; it < 15; ++it) {
                const float tau = 0.5f * (lo + hi);
                float s = 0.f;
#pragma unroll
                for (int j = 0; j < 8; ++j) {
                    s += fmaxf(zv[j].x - tau, 0.f) + fmaxf(zv[j].y - tau, 0.f)
                       + fmaxf(zv[j].z - tau, 0.f) + fmaxf(zv[j].w - tau, 0.f);
                }
#pragma unroll
                for (int off = 16; off; off >>= 1) s += __shfl_xor_sync(~0u, s, off);
                if (s >= 1.f) lo = tau; else hi = tau;
            }
            const float tau = 0.5f * (lo + hi);
            float s = 0.f, k = 0.f;
#pragma unroll
            for (int j = 0; j < 8; ++j) {
                if (zv[j].x > tau) { s += zv[j].x; k += 1.f; }
                if (zv[j].y > tau) { s += zv[j].y; k += 1.f; }
                if (zv[j].z > tau) { s += zv[j].z; k += 1.f; }
                if (zv[j].w > tau) { s += zv[j].w; k += 1.f; }
            }
#pragma unroll
            for (int off = 16; off; off >>= 1) {
                s += __shfl_xor_sync(~0u, s, off);
                k += __shfl_xor_sync(~0u, k, off);
            }
            if (lane == 0) tau_s[row] = (s - 1.f) / k;
        }
        __syncthreads();
    }

    // per-warp tau registers (constant over K)
    float taur[2][2] = {{0.f, 0.f}, {0.f, 0.f}};
    if (MODE == M_SPMAX) {
#pragma unroll
        for (int mi = 0; mi < 2; ++mi) {
            taur[mi][0] = tau_s[wr * 32 + mi * 16 + g];
            taur[mi][1] = tau_s[wr * 32 + mi * 16 + g + 8];
        }
    }

    float acc[2][NI][4];
#pragma unroll
    for (int mi = 0; mi < 2; ++mi)
#pragma unroll
        for (int ni = 0; ni < NI; ++ni)
#pragma unroll
            for (int j = 0; j < 4; ++j) acc[mi][ni][j] = 0.f;

    for (int i = 0; i < niter; ++i) {
        if (i + 1 < niter) {
            load_stage((i + 1) & 1, i + 1);
            asm volatile("cp.async.wait_group 1;" ::: "memory");
        } else {
            asm volatile("cp.async.wait_group 0;" ::: "memory");
        }
        __syncthreads();

        const float* As = smem + (i & 1) * STAGE_F;
        const float* Bs = As + BM * PITCH;

#pragma unroll
        for (int ks = 0; ks < 2; ++ks) {      // two k16 steps per K=32 chunk
            const int kk = ks * 16 + 2 * c;
            uint32_t ah[2][4], al[2][4];
#pragma unroll
            for (int mi = 0; mi < 2; ++mi) {
                const int rb = (wr * 32 + mi * 16 + g) * PITCH + kk;
                float2 v0 = *(const float2*)&As[rb];
                float2 v1 = *(const float2*)&As[rb + 8 * PITCH];
                float2 v2 = *(const float2*)&As[rb + 8];
                float2 v3 = *(const float2*)&As[rb + 8 * PITCH + 8];
                if (MODE == M_SPMAX) {
                    const float t0 = taur[mi][0], t1 = taur[mi][1];
                    v0.x = fmaxf(v0.x - t0, 0.f); v0.y = fmaxf(v0.y - t0, 0.f);
                    v1.x = fmaxf(v1.x - t1, 0.f); v1.y = fmaxf(v1.y - t1, 0.f);
                    v2.x = fmaxf(v2.x - t0, 0.f); v2.y = fmaxf(v2.y - t0, 0.f);
                    v3.x = fmaxf(v3.x - t1, 0.f); v3.y = fmaxf(v3.y - t1, 0.f);
                }
                split2(v0, ah[mi][0], al[mi][0]);
                split2(v1, ah[mi][1], al[mi][1]);
                split2(v2, ah[mi][2], al[mi][2]);
                split2(v3, ah[mi][3], al[mi][3]);
            }
            uint32_t bh[NI][2], bl[NI][2];
#pragma unroll
            for (int ni = 0; ni < NI; ++ni) {
                const int rb = (wc * WN + ni * 8 + g) * PITCH + kk;
                split2(*(const float2*)&Bs[rb],     bh[ni][0], bl[ni][0]);
                split2(*(const float2*)&Bs[rb + 8], bh[ni][1], bl[ni][1]);
            }
#pragma unroll
            for (int mi = 0; mi < 2; ++mi)
#pragma unroll
                for (int ni = 0; ni < NI; ++ni) {
                    mma16(acc[mi][ni], al[mi], bh[ni]);
                    mma16(acc[mi][ni], ah[mi], bl[ni]);
                    mma16(acc[mi][ni], ah[mi], bh[ni]);
                }
        }
        __syncthreads();
    }

    // ---- epilogue ----
#pragma unroll
    for (int mi = 0; mi < 2; ++mi) {
#pragma unroll
        for (int ni = 0; ni < NI; ++ni) {
            const long col = n0 + wc * WN + ni * 8 + 2 * c;
#pragma unroll
            for (int h = 0; h < 2; ++h) {
                const long row = m0 + wr * 32 + mi * 16 + g + h * 8;
                float vx = acc[mi][ni][2 * h];
                float vy = acc[mi][ni][2 * h + 1];
                if (MODE == M_GEGLU) {
                    const long j = col >> 1;
                    const float a  = vx + bias[j];
                    const float gg = vy + bias[j + FF];
                    C[row * ldc + j] = a * gg * normcdff(gg);
                } else {
                    vx *= alpha; vy *= alpha;
                    if (bias) {
                        float2 bv = *(const float2*)&bias[col];
                        vx += bv.x; vy += bv.y;
                    }
                    const long off = row * ldc + col;
                    if (Rz) {
                        float2 rv = *(const float2*)&Rz[off];
                        vx += rv.x; vy += rv.y;
                    }
                    if (pos) {
                        float2 pv = *(const float2*)&pos[(row & (SEQ - 1)) * D_MODEL + col];
                        vx += pv.x; vy += pv.y;
                    }
                    *(float2*)&C[off] = make_float2(vx, vy);
                }
            }
        }
    }
}

// ---------------------------------------------------------------------------
__global__ void __launch_bounds__(256)
transpose_kernel(const float* __restrict__ in, long ldi, long iO, long iI,
                 float* __restrict__ out, long ldo, long oO, long oI)
{
    __shared__ float tile[32][33];
    const int z = blockIdx.z;
    in  += (z >> 3) * iO + (z & 7) * iI;
    out += (z >> 3) * oO + (z & 7) * oI;
    const long r0 = (long)blockIdx.y * 32, c0 = (long)blockIdx.x * 32;
#pragma unroll
    for (int i = 0; i < 32; i += 8)
        tile[threadIdx.y + i][threadIdx.x] =
            in[(r0 + threadIdx.y + i) * ldi + c0 + threadIdx.x];
    __syncthreads();
#pragma unroll
    for (int i = 0; i < 32; i += 8)
        out[(c0 + threadIdx.y + i) * ldo + r0 + threadIdx.x] =
            tile[threadIdx.x][threadIdx.y + i];
}

// W1 transpose with a/g interleave: in = w1[l] as [512, 4096]; out row for
// orig col n is (n < FF) ? 2n : 2(n-FF)+1; out is [4096, 512].
__global__ void __launch_bounds__(256)
transpose_w1_kernel(const float* __restrict__ in, float* __restrict__ out)
{
    __shared__ float tile[32][33];
    const int z = blockIdx.z;                   // layer
    in  += (long)z * D_MODEL * (2 * FF);
    out += (long)z * (2 * FF) * D_MODEL;
    const long r0 = (long)blockIdx.y * 32;      // k block
    const long c0 = (long)blockIdx.x * 32;      // n block
#pragma unroll
    for (int i = 0; i < 32; i += 8)
        tile[threadIdx.y + i][threadIdx.x] =
            in[(r0 + threadIdx.y + i) * (2 * FF) + c0 + threadIdx.x];
    __syncthreads();
#pragma unroll
    for (int i = 0; i < 32; i += 8) {
        const long n = c0 + threadIdx.y + i;
        const long r_out = (n < FF) ? 2 * n : 2 * (n - FF) + 1;
        out[r_out * D_MODEL + r0 + threadIdx.x] = tile[threadIdx.x][threadIdx.y + i];
    }
}

// ---------------------------------------------------------------------------
__global__ void __launch_bounds__(128)
ln_kernel(const float* __restrict__ x, const float* __restrict__ g,
          const float* __restrict__ b, float* __restrict__ o)
{
    __shared__ float sh[4];
    const long row = blockIdx.x;
    const int  t   = threadIdx.x;
    float4 v = ((const float4*)(x + row * D_MODEL))[t];

    float s = v.x + v.y + v.z + v.w;
#pragma unroll
    for (int off = 16; off; off >>= 1) s += __shfl_xor_sync(~0u, s, off);
    if ((t & 31) == 0) sh[t >> 5] = s;
    __syncthreads();
    const float mu = (sh[0] + sh[1] + sh[2] + sh[3]) * (1.f / D_MODEL);

    const float dx = v.x - mu, dy = v.y - mu, dz = v.z - mu, dw = v.w - mu;
    float s2 = dx * dx + dy * dy + dz * dz + dw * dw;
#pragma unroll
    for (int off = 16; off; off >>= 1) s2 += __shfl_xor_sync(~0u, s2, off);
    __syncthreads();
    if ((t & 31) == 0) sh[t >> 5] = s2;
    __syncthreads();
    const float var = (sh[0] + sh[1] + sh[2] + sh[3]) * (1.f / D_MODEL);
    const float r   = rsqrtf(var + 1e-5f);

    float4 gg = ((const float4*)g)[t];
    float4 bb = ((const float4*)b)[t];
    float4 ov;
    ov.x = dx * r * gg.x + bb.x;
    ov.y = dy * r * gg.y + bb.y;
    ov.z = dz * r * gg.z + bb.z;
    ov.w = dw * r * gg.w + bb.w;
    ((float4*)(o + row * D_MODEL))[t] = ov;
}

// ---------------------------------------------------------------------------
__global__ void __launch_bounds__(512)
pool1_kernel(const float* __restrict__ x, float* __restrict__ p)
{
    const int b = blockIdx.x, cc = blockIdx.y;
    const int d = threadIdx.x;
    float s = 0.f;
    const float* base = x + ((long)b * SEQ + cc * 128) * D_MODEL + d;
    for (int i = 0; i < 128; ++i) s += base[(long)i * D_MODEL];
    p[(b * 8 + cc) * D_MODEL + d] = s;
}

__global__ void __launch_bounds__(256)
pool2_kernel(const float* __restrict__ p, float* __restrict__ o)
{
    const int i = blockIdx.x * blockDim.x + threadIdx.x;
    const int b = i >> 9, d = i & 511;
    float s = 0.f;
#pragma unroll
    for (int cc = 0; cc < 8; ++cc) s += p[(b * 8 + cc) * D_MODEL + d];
    o[i] = s * (1.f / SEQ);
}

// ---------------------------------------------------------------------------
#define SMEM_BN128 (2 * (128 + 128) * 160)
#define SMEM_BN64  (2 * (128 +  64) * 160 + 512)

template<int BN, int MODE>
static void launch_mg(const float* A, long lda, long aO, long aI,
                      const float* B, long ldb, long bO, long bI,
                      float* C, long ldc, long cO, long cI,
                      int M, int N, int K, int batches,
                      const float* bias, const float* resid,
                      const float* pos, float alpha)
{
    dim3 grid(N / BN, M / 128, batches);
    const int smem = (BN == 128) ? SMEM_BN128 : SMEM_BN64;
    mgemm_kernel<BN, MODE><<<grid, 256, smem>>>(A, lda, aO, aI, B, ldb, bO, bI,
                                                C, ldc, cO, cI, K, bias, resid,
                                                pos, alpha);
}

extern "C" void kernel_launch(void* const* d_in, const int* in_sizes, int n_in,
                              void* d_out, int out_size)
{
    const float* x      = (const float*)d_in[0];
    const float* proj_w = (const float*)d_in[1];
    const float* proj_b = (const float*)d_in[2];
    const float* pos    = (const float*)d_in[3];
    const float* ln1_g  = (const float*)d_in[4];
    const float* ln1_b  = (const float*)d_in[5];
    const float* wqkv   = (const float*)d_in[6];
    const float* wout   = (const float*)d_in[7];
    const float* bout   = (const float*)d_in[8];
    const float* ln2_g  = (const float*)d_in[9];
    const float* ln2_b  = (const float*)d_in[10];
    const float* w1     = (const float*)d_in[11];
    const float* b1     = (const float*)d_in[12];
    const float* w2     = (const float*)d_in[13];
    const float* b2     = (const float*)d_in[14];
    float* out = (float*)d_out;

    cudaFuncSetAttribute(mgemm_kernel<128, M_PLAIN>,
                         cudaFuncAttributeMaxDynamicSharedMemorySize, SMEM_BN128);
    cudaFuncSetAttribute(mgemm_kernel<128, M_GEGLU>,
                         cudaFuncAttributeMaxDynamicSharedMemorySize, SMEM_BN128);
    cudaFuncSetAttribute(mgemm_kernel<64, M_SPMAX>,
                         cudaFuncAttributeMaxDynamicSharedMemorySize, SMEM_BN64);

    float *gx, *gh, *gqkv, *gsim, *gao, *gffg, *gpool, *gwt, *gvt;
    cudaGetSymbolAddress((void**)&gx,    g_x);
    cudaGetSymbolAddress((void**)&gh,    g_h);
    cudaGetSymbolAddress((void**)&gqkv,  g_qkv);
    cudaGetSymbolAddress((void**)&gsim,  g_sim);
    cudaGetSymbolAddress((void**)&gao,   g_ao);
    cudaGetSymbolAddress((void**)&gffg,  g_ffg);
    cudaGetSymbolAddress((void**)&gpool, g_pool);
    cudaGetSymbolAddress((void**)&gwt,   g_wt);
    cudaGetSymbolAddress((void**)&gvt,   g_vt);

    // ---- weight transposes (B operands as [N,K] row-major) ----
    transpose_kernel<<<dim3(16, 16, 1), dim3(32, 8)>>>(
        proj_w, D_MODEL, 0, 0, gwt + OFF_PROJ, D_MODEL, 0, 0);
    transpose_kernel<<<dim3(48, 16, 3), dim3(32, 8)>>>(
        wqkv, 3 * D_MODEL, 0, (long)D_MODEL * 3 * D_MODEL,
        gwt + OFF_QKV, D_MODEL, 0, (long)3 * D_MODEL * D_MODEL);
    transpose_kernel<<<dim3(16, 16, 3), dim3(32, 8)>>>(
        wout, D_MODEL, 0, (long)D_MODEL * D_MODEL,
        gwt + OFF_WOUT, D_MODEL, 0, (long)D_MODEL * D_MODEL);
    transpose_w1_kernel<<<dim3(128, 16, 3), dim3(32, 8)>>>(w1, gwt + OFF_W1);
    transpose_kernel<<<dim3(16, 64, 3), dim3(32, 8)>>>(
        w2, D_MODEL, 0, (long)FF * D_MODEL,
        gwt + OFF_W2, FF, 0, (long)D_MODEL * FF);

    // x = x @ proj_w + proj_b + pos
    launch_mg<128, M_PLAIN>(x, D_MODEL, 0, 0, gwt + OFF_PROJ, D_MODEL, 0, 0,
                            gx, D_MODEL, 0, 0, NROWS, D_MODEL, D_MODEL, 1,
                            proj_b, nullptr, pos, 1.f);

    const float scale = 0.125f;

    for (int l = 0; l < NDEPTH; ++l) {
        ln_kernel<<<NROWS, 128>>>(gx, ln1_g + l * D_MODEL, ln1_b + l * D_MODEL, gh);

        // qkv = h @ Wqkv
        launch_mg<128, M_PLAIN>(gh, D_MODEL, 0, 0,
                                gwt + OFF_QKV + (long)l * 3 * D_MODEL * D_MODEL, D_MODEL, 0, 0,
                                gqkv, 3 * D_MODEL, 0, 0,
                                NROWS, 3 * D_MODEL, D_MODEL, 1, nullptr, nullptr, nullptr, 1.f);

        // V^T per (b,h): [1024,64] -> [64,1024]
        transpose_kernel<<<dim3(2, 32, NB * NHEADS), dim3(32, 8)>>>(
            gqkv + 2 * D_MODEL, 3 * D_MODEL, (long)SEQ * 3 * D_MODEL, DHEAD,
            gvt, SEQ, (long)NHEADS * DHEAD * SEQ, (long)DHEAD * SEQ);

        // sim = q @ k^T * scale
        launch_mg<128, M_PLAIN>(gqkv,           3 * D_MODEL, (long)SEQ * 3 * D_MODEL, DHEAD,
                                gqkv + D_MODEL, 3 * D_MODEL, (long)SEQ * 3 * D_MODEL, DHEAD,
                                gsim, SEQ, (long)NHEADS * SEQ * SEQ, (long)SEQ * SEQ,
                                SEQ, SEQ, DHEAD, NB * NHEADS,
                                nullptr, nullptr, nullptr, scale);

        // ao = sparsemax(sim) @ v   (sparsemax fused into GEMM prologue)
        launch_mg<64, M_SPMAX>(gsim, SEQ, (long)NHEADS * SEQ * SEQ, (long)SEQ * SEQ,
                               gvt,  SEQ, (long)NHEADS * DHEAD * SEQ, (long)DHEAD * SEQ,
                               gao, D_MODEL, (long)SEQ * D_MODEL, DHEAD,
                               SEQ, DHEAD, SEQ, NB * NHEADS,
                               nullptr, nullptr, nullptr, 1.f);

        // x = x + ao @ Wout + bout
        launch_mg<128, M_PLAIN>(gao, D_MODEL, 0, 0,
                                gwt + OFF_WOUT + (long)l * D_MODEL * D_MODEL, D_MODEL, 0, 0,
                                gx, D_MODEL, 0, 0, NROWS, D_MODEL, D_MODEL, 1,
                                bout + l * D_MODEL, gx, nullptr, 1.f);

        ln_kernel<<<NROWS, 128>>>(gx, ln2_g + l * D_MODEL, ln2_b + l * D_MODEL, gh);

        // ffg = GEGLU(h @ W1 + b1)   (fused epilogue; W1 interleaved a/g)
        launch_mg<128, M_GEGLU>(gh, D_MODEL, 0, 0,
                                gwt + OFF_W1 + (long)l * 2 * FF * D_MODEL, D_MODEL, 0, 0,
                                gffg, FF, 0, 0, NROWS, 2 * FF, D_MODEL, 1,
                                b1 + (long)l * 2 * FF, nullptr, nullptr, 1.f);

        // x = x + ffg @ W2 + b2
        launch_mg<128, M_PLAIN>(gffg, FF, 0, 0,
                                gwt + OFF_W2 + (long)l * D_MODEL * FF, FF, 0, 0,
                                gx, D_MODEL, 0, 0, NROWS, D_MODEL, FF, 1,
                                b2 + l * D_MODEL, gx, nullptr, 1.f);
    }

    pool1_kernel<<<dim3(NB, 8), 512>>>(gx, gpool);
    pool2_kernel<<<16, 256>>>(gpool, out);
}

// round 9
// speedup vs baseline: 1.1246x; 1.1246x over previous
#include <cuda_runtime.h>
#include <cmath>
#include <cstdint>

#define D_MODEL 512
#define SEQ     1024
#define NB      8
#define NHEADS  8
#define DHEAD   64
#define FF      2048
#define NROWS   (NB*SEQ)    /* 8192 */
#define NDEPTH  3

// ---------------- scratch (device globals; no allocation allowed) ----------
__device__ float g_x   [NROWS * D_MODEL];
__device__ float g_h   [NROWS * D_MODEL];
__device__ float g_qkv [NROWS * 3 * D_MODEL];
__device__ float g_sim [67108864];                 // 64 * 1024 * 1024
__device__ float g_ao  [NROWS * D_MODEL];
__device__ float g_ffg [NROWS * FF];
__device__ float g_pool[NB * 8 * D_MODEL];
__device__ float g_wt  [12845056];                 // transposed weights (fp32)
__device__ float g_ws  [12845056];                 // split bf16 hi/lo weight planes
__device__ float g_vt  [NB * NHEADS * DHEAD * SEQ];// V^T per (b,h): [64][1024]

#define OFF_PROJ 0
#define OFF_QKV  262144
#define OFF_WOUT 2621440
#define OFF_W1   3407872
#define OFF_W2   9699328

// GEMM modes
#define M_PLAIN 0
#define M_GEGLU 1

// ---------------------------------------------------------------------------
__device__ __forceinline__ void cp16(uint32_t sa, const float* ga) {
    asm volatile("cp.async.cg.shared.global [%0], [%1], 16;" :: "r"(sa), "l"(ga) : "memory");
}
__device__ __forceinline__ uint32_t smem_u32(const void* p) {
    uint32_t a;
    asm("{ .reg .u64 t; cvta.to.shared.u64 t, %1; cvt.u32.u64 %0, t; }"
        : "=r"(a) : "l"(p));
    return a;
}
__device__ __forceinline__ void cp_commit() {
    asm volatile("cp.async.commit_group;" ::: "memory");
}
// bf16x3 MMA: m16n8k16, row.col, f32 accum
__device__ __forceinline__ void mma16(float* d, const uint32_t* a, const uint32_t* b) {
    asm volatile(
        "mma.sync.aligned.m16n8k16.row.col.f32.bf16.bf16.f32 "
        "{%0,%1,%2,%3}, {%4,%5,%6,%7}, {%8,%9}, {%0,%1,%2,%3};"
        : "+f"(d[0]), "+f"(d[1]), "+f"(d[2]), "+f"(d[3])
        : "r"(a[0]), "r"(a[1]), "r"(a[2]), "r"(a[3]), "r"(b[0]), "r"(b[1]));
}
// split float2 -> packed bf16 hi pair + packed bf16 lo pair
// (v.x -> low 16 bits, v.y -> high 16 bits, matching k, k+1 fragment order)
__device__ __forceinline__ void split2(float2 v, uint32_t& hi, uint32_t& lo) {
    asm("cvt.rn.bf16x2.f32 %0, %1, %2;" : "=r"(hi) : "f"(v.y), "f"(v.x));
    const float h0 = __uint_as_float(hi << 16);
    const float h1 = __uint_as_float(hi & 0xFFFF0000u);
    const float r0 = v.x - h0;
    const float r1 = v.y - h1;
    asm("cvt.rn.bf16x2.f32 %0, %1, %2;" : "=r"(lo) : "f"(r1), "f"(r0));
}

// ---------------------------------------------------------------------------
// bf16x3 mma.sync GEMM:  C[M,N] = alpha * A[M,K] @ Bt[N,K]^T (+bias+resid+pos)
// MODE == M_GEGLU: B cols interleaved (a0,g0,...); epilogue stores
//   (a+b_a)*gelu(g+b_g) at C[row, col/2], ldc = FF.
// BSPLIT: B is a pre-split bf16 buffer: per row, per 32-k chunk (128B):
//   16 words of packed (k,k+1) hi pairs, then 16 words of lo pairs.
//   Same bytes-per-row as fp32, so the stage loader is identical; only the
//   fragment path changes (LDS.32 instead of fp32 load + split2).
// ---------------------------------------------------------------------------
template<int BN, int MODE, bool BSPLIT>
__global__ void __launch_bounds__(256, 2)
mgemm_kernel(const float* __restrict__ A, long lda, long aO, long aI,
             const float* __restrict__ B, long ldb, long bO, long bI,
             float* __restrict__ C, long ldc, long cO, long cI,
             int K,
             const float* __restrict__ bias,
             const float* __restrict__ resid,
             const float* __restrict__ pos,
             float alpha)
{
    constexpr int BM = 128;
    constexpr int WN = BN / 2;       // warp tile: 32 x WN (4x2 warp grid)
    constexpr int NI = WN / 8;       // n-tiles per warp
    constexpr int PITCH = 40;        // floats per smem row (160B)
    constexpr int STAGE_F = (BM + BN) * PITCH;

    extern __shared__ float smem[];

    const int z = blockIdx.z, zo = z >> 3, zi = z & 7;
    A += zo * aO + zi * aI;
    B += zo * bO + zi * bI;
    C += zo * cO + zi * cI;
    const float* Rz = resid ? resid + zo * cO + zi * cI : nullptr;

    const long m0 = (long)blockIdx.y * BM;
    const long n0 = (long)blockIdx.x * BN;
    A += m0 * lda;
    B += n0 * ldb;

    const int t    = threadIdx.x;
    const int wid  = t >> 5, lane = t & 31;
    const int wr   = wid & 3, wc = wid >> 2;
    const int g    = lane >> 2, c = lane & 3;

    const uint32_t sbase = smem_u32(smem);
    const int niter = K >> 5;        // chunks of K=32

    auto load_stage = [&](int s, int kc) {
        const uint32_t sA = sbase + (uint32_t)(s * STAGE_F) * 4u;
        const uint32_t sB = sA + BM * PITCH * 4u;
        const float* ga = A + kc * 32;
        const float* gb = B + kc * 32;   // 128B per 32-k chunk in both layouts
        const int r0  = t >> 3;
        const int seg = (t & 7) * 16;
#pragma unroll
        for (int p = 0; p < BM / 32; ++p) {
            const int r = p * 32 + r0;
            cp16(sA + r * 160 + seg, ga + (long)r * lda + (t & 7) * 4);
        }
#pragma unroll
        for (int p = 0; p < BN / 32; ++p) {
            const int r = p * 32 + r0;
            cp16(sB + r * 160 + seg, gb + (long)r * ldb + (t & 7) * 4);
        }
        cp_commit();
    };

    float acc[2][NI][4];
#pragma unroll
    for (int mi = 0; mi < 2; ++mi)
#pragma unroll
        for (int ni = 0; ni < NI; ++ni)
#pragma unroll
            for (int j = 0; j < 4; ++j) acc[mi][ni][j] = 0.f;

    load_stage(0, 0);

    for (int i = 0; i < niter; ++i) {
        if (i + 1 < niter) {
            load_stage((i + 1) & 1, i + 1);
            asm volatile("cp.async.wait_group 1;" ::: "memory");
        } else {
            asm volatile("cp.async.wait_group 0;" ::: "memory");
        }
        __syncthreads();

        const float* As = smem + (i & 1) * STAGE_F;
        const float* Bs = As + BM * PITCH;
        const uint32_t* Bu = (const uint32_t*)Bs;

#pragma unroll
        for (int ks = 0; ks < 2; ++ks) {      // two k16 steps per K=32 chunk
            const int kk = ks * 16 + 2 * c;
            uint32_t ah[2][4], al[2][4];
#pragma unroll
            for (int mi = 0; mi < 2; ++mi) {
                const int rb = (wr * 32 + mi * 16 + g) * PITCH + kk;
                split2(*(const float2*)&As[rb],                 ah[mi][0], al[mi][0]);
                split2(*(const float2*)&As[rb + 8 * PITCH],     ah[mi][1], al[mi][1]);
                split2(*(const float2*)&As[rb + 8],             ah[mi][2], al[mi][2]);
                split2(*(const float2*)&As[rb + 8 * PITCH + 8], ah[mi][3], al[mi][3]);
            }
            uint32_t bh[NI][2], bl[NI][2];
#pragma unroll
            for (int ni = 0; ni < NI; ++ni) {
                if (BSPLIT) {
                    const int rb2 = (wc * WN + ni * 8 + g) * PITCH + ks * 8 + c;
                    bh[ni][0] = Bu[rb2];
                    bh[ni][1] = Bu[rb2 + 4];
                    bl[ni][0] = Bu[rb2 + 16];
                    bl[ni][1] = Bu[rb2 + 20];
                } else {
                    const int rb = (wc * WN + ni * 8 + g) * PITCH + kk;
                    split2(*(const float2*)&Bs[rb],     bh[ni][0], bl[ni][0]);
                    split2(*(const float2*)&Bs[rb + 8], bh[ni][1], bl[ni][1]);
                }
            }
#pragma unroll
            for (int mi = 0; mi < 2; ++mi)
#pragma unroll
                for (int ni = 0; ni < NI; ++ni) {
                    mma16(acc[mi][ni], al[mi], bh[ni]);
                    mma16(acc[mi][ni], ah[mi], bl[ni]);
                    mma16(acc[mi][ni], ah[mi], bh[ni]);
                }
        }
        __syncthreads();
    }

    // ---- epilogue ----
#pragma unroll
    for (int mi = 0; mi < 2; ++mi) {
#pragma unroll
        for (int ni = 0; ni < NI; ++ni) {
            const long col = n0 + wc * WN + ni * 8 + 2 * c;
#pragma unroll
            for (int h = 0; h < 2; ++h) {
                const long row = m0 + wr * 32 + mi * 16 + g + h * 8;
                float vx = acc[mi][ni][2 * h];
                float vy = acc[mi][ni][2 * h + 1];
                if (MODE == M_GEGLU) {
                    const long j = col >> 1;
                    const float a  = vx + bias[j];
                    const float gg = vy + bias[j + FF];
                    C[row * ldc + j] = a * gg * normcdff(gg);
                } else {
                    vx *= alpha; vy *= alpha;
                    if (bias) {
                        float2 bv = *(const float2*)&bias[col];
                        vx += bv.x; vy += bv.y;
                    }
                    const long off = row * ldc + col;
                    if (Rz) {
                        float2 rv = *(const float2*)&Rz[off];
                        vx += rv.x; vy += rv.y;
                    }
                    if (pos) {
                        float2 pv = *(const float2*)&pos[(row & (SEQ - 1)) * D_MODEL + col];
                        vx += pv.x; vy += pv.y;
                    }
                    *(float2*)&C[off] = make_float2(vx, vy);
                }
            }
        }
    }
}

// ---------------------------------------------------------------------------
// Convert fp32 [N,K] row-major -> split bf16 layout (per row, per 32-k chunk:
// 16 words hi pairs then 16 words lo pairs). One thread per (row, k-pair).
// ---------------------------------------------------------------------------
__global__ void __launch_bounds__(256)
split_weights_kernel(const float* __restrict__ in, uint32_t* __restrict__ out,
                     int K, long total_pairs)
{
    const long idx = (long)blockIdx.x * 256 + threadIdx.x;
    if (idx >= total_pairs) return;
    const int  kp   = K >> 1;
    const long row  = idx / kp;
    const int  pid  = (int)(idx - row * kp);
    const int  kc   = pid >> 4;          // 16 pairs per 32-k chunk
    const int  pl   = pid & 15;
    const int  k0   = kc * 32 + pl * 2;
    float2 v = *(const float2*)&in[row * K + k0];
    uint32_t hi, lo;
    split2(v, hi, lo);
    out[row * K + kc * 32 + pl]      = hi;
    out[row * K + kc * 32 + 16 + pl] = lo;
}

// ---------------------------------------------------------------------------
__global__ void __launch_bounds__(256)
transpose_kernel(const float* __restrict__ in, long ldi, long iO, long iI,
                 float* __restrict__ out, long ldo, long oO, long oI)
{
    __shared__ float tile[32][33];
    const int z = blockIdx.z;
    in  += (z >> 3) * iO + (z & 7) * iI;
    out += (z >> 3) * oO + (z & 7) * oI;
    const long r0 = (long)blockIdx.y * 32, c0 = (long)blockIdx.x * 32;
#pragma unroll
    for (int i = 0; i < 32; i += 8)
        tile[threadIdx.y + i][threadIdx.x] =
            in[(r0 + threadIdx.y + i) * ldi + c0 + threadIdx.x];
    __syncthreads();
#pragma unroll
    for (int i = 0; i < 32; i += 8)
        out[(c0 + threadIdx.y + i) * ldo + r0 + threadIdx.x] =
            tile[threadIdx.x][threadIdx.y + i];
}

// W1 transpose with a/g interleave
__global__ void __launch_bounds__(256)
transpose_w1_kernel(const float* __restrict__ in, float* __restrict__ out)
{
    __shared__ float tile[32][33];
    const int z = blockIdx.z;                   // layer
    in  += (long)z * D_MODEL * (2 * FF);
    out += (long)z * (2 * FF) * D_MODEL;
    const long r0 = (long)blockIdx.y * 32;      // k block
    const long c0 = (long)blockIdx.x * 32;      // n block
#pragma unroll
    for (int i = 0; i < 32; i += 8)
        tile[threadIdx.y + i][threadIdx.x] =
            in[(r0 + threadIdx.y + i) * (2 * FF) + c0 + threadIdx.x];
    __syncthreads();
#pragma unroll
    for (int i = 0; i < 32; i += 8) {
        const long n = c0 + threadIdx.y + i;
        const long r_out = (n < FF) ? 2 * n : 2 * (n - FF) + 1;
        out[r_out * D_MODEL + r0 + threadIdx.x] = tile[threadIdx.x][threadIdx.y + i];
    }
}

// ---------------------------------------------------------------------------
__global__ void __launch_bounds__(128)
ln_kernel(const float* __restrict__ x, const float* __restrict__ g,
          const float* __restrict__ b, float* __restrict__ o)
{
    __shared__ float sh[4];
    const long row = blockIdx.x;
    const int  t   = threadIdx.x;
    float4 v = ((const float4*)(x + row * D_MODEL))[t];

    float s = v.x + v.y + v.z + v.w;
#pragma unroll
    for (int off = 16; off; off >>= 1) s += __shfl_xor_sync(~0u, s, off);
    if ((t & 31) == 0) sh[t >> 5] = s;
    __syncthreads();
    const float mu = (sh[0] + sh[1] + sh[2] + sh[3]) * (1.f / D_MODEL);

    const float dx = v.x - mu, dy = v.y - mu, dz = v.z - mu, dw = v.w - mu;
    float s2 = dx * dx + dy * dy + dz * dz + dw * dw;
#pragma unroll
    for (int off = 16; off; off >>= 1) s2 += __shfl_xor_sync(~0u, s2, off);
    __syncthreads();
    if ((t & 31) == 0) sh[t >> 5] = s2;
    __syncthreads();
    const float var = (sh[0] + sh[1] + sh[2] + sh[3]) * (1.f / D_MODEL);
    const float r   = rsqrtf(var + 1e-5f);

    float4 gg = ((const float4*)g)[t];
    float4 bb = ((const float4*)b)[t];
    float4 ov;
    ov.x = dx * r * gg.x + bb.x;
    ov.y = dy * r * gg.y + bb.y;
    ov.z = dz * r * gg.z + bb.z;
    ov.w = dw * r * gg.w + bb.w;
    ((float4*)(o + row * D_MODEL))[t] = ov;
}

// ---------------------------------------------------------------------------
// Sparsemax, warp-per-row: 15-iter bisection + one exact Michelot refinement.
// ---------------------------------------------------------------------------
__global__ void __launch_bounds__(256)
sparsemax_kernel(float* __restrict__ sim)
{
    const long row  = (long)blockIdx.x * 8 + (threadIdx.x >> 5);
    const int  lane = threadIdx.x & 31;
    float4* base = (float4*)(sim + row * (long)SEQ);

    float4 z[8];
#pragma unroll
    for (int j = 0; j < 8; ++j) z[j] = base[j * 32 + lane];

    float m = -1e30f;
#pragma unroll
    for (int j = 0; j < 8; ++j)
        m = fmaxf(m, fmaxf(fmaxf(z[j].x, z[j].y), fmaxf(z[j].z, z[j].w)));
#pragma unroll
    for (int off = 16; off; off >>= 1) m = fmaxf(m, __shfl_xor_sync(~0u, m, off));

    float lo = m - 1.f, hi = m;
#pragma unroll 1
    for (int it = 0; it < 15; ++it) {
        const float tau = 0.5f * (lo + hi);
        float s = 0.f;
#pragma unroll
        for (int j = 0; j < 8; ++j) {
            s += fmaxf(z[j].x - tau, 0.f) + fmaxf(z[j].y - tau, 0.f)
               + fmaxf(z[j].z - tau, 0.f) + fmaxf(z[j].w - tau, 0.f);
        }
#pragma unroll
        for (int off = 16; off; off >>= 1) s += __shfl_xor_sync(~0u, s, off);
        if (s >= 1.f) lo = tau; else hi = tau;
    }
    // exact refinement on the pinned active set
    {
        const float tau = 0.5f * (lo + hi);
        float s = 0.f, k = 0.f;
#pragma unroll
        for (int j = 0; j < 8; ++j) {
            if (z[j].x > tau) { s += z[j].x; k += 1.f; }
            if (z[j].y > tau) { s += z[j].y; k += 1.f; }
            if (z[j].z > tau) { s += z[j].z; k += 1.f; }
            if (z[j].w > tau) { s += z[j].w; k += 1.f; }
        }
#pragma unroll
        for (int off = 16; off; off >>= 1) {
            s += __shfl_xor_sync(~0u, s, off);
            k += __shfl_xor_sync(~0u, k, off);
        }
        const float tau_x = (s - 1.f) / k;
#pragma unroll
        for (int j = 0; j < 8; ++j) {
            float4 o;
            o.x = fmaxf(z[j].x - tau_x, 0.f);
            o.y = fmaxf(z[j].y - tau_x, 0.f);
            o.z = fmaxf(z[j].z - tau_x, 0.f);
            o.w = fmaxf(z[j].w - tau_x, 0.f);
            base[j * 32 + lane] = o;
        }
    }
}

// ---------------------------------------------------------------------------
__global__ void __launch_bounds__(512)
pool1_kernel(const float* __restrict__ x, float* __restrict__ p)
{
    const int b = blockIdx.x, cc = blockIdx.y;
    const int d = threadIdx.x;
    float s = 0.f;
    const float* base = x + ((long)b * SEQ + cc * 128) * D_MODEL + d;
    for (int i = 0; i < 128; ++i) s += base[(long)i * D_MODEL];
    p[(b * 8 + cc) * D_MODEL + d] = s;
}

__global__ void __launch_bounds__(256)
pool2_kernel(const float* __restrict__ p, float* __restrict__ o)
{
    const int i = blockIdx.x * blockDim.x + threadIdx.x;
    const int b = i >> 9, d = i & 511;
    float s = 0.f;
#pragma unroll
    for (int cc = 0; cc < 8; ++cc) s += p[(b * 8 + cc) * D_MODEL + d];
    o[i] = s * (1.f / SEQ);
}

// ---------------------------------------------------------------------------
#define SMEM_BN128 (2 * (128 + 128) * 160)
#define SMEM_BN64  (2 * (128 +  64) * 160)

template<int BN, int MODE, bool BSPLIT>
static void launch_mg(const float* A, long lda, long aO, long aI,
                      const float* B, long ldb, long bO, long bI,
                      float* C, long ldc, long cO, long cI,
                      int M, int N, int K, int batches,
                      const float* bias, const float* resid,
                      const float* pos, float alpha)
{
    dim3 grid(N / BN, M / 128, batches);
    const int smem = (BN == 128) ? SMEM_BN128 : SMEM_BN64;
    mgemm_kernel<BN, MODE, BSPLIT><<<grid, 256, smem>>>(
        A, lda, aO, aI, B, ldb, bO, bI, C, ldc, cO, cI, K, bias, resid, pos, alpha);
}

extern "C" void kernel_launch(void* const* d_in, const int* in_sizes, int n_in,
                              void* d_out, int out_size)
{
    const float* x      = (const float*)d_in[0];
    const float* proj_w = (const float*)d_in[1];
    const float* proj_b = (const float*)d_in[2];
    const float* pos    = (const float*)d_in[3];
    const float* ln1_g  = (const float*)d_in[4];
    const float* ln1_b  = (const float*)d_in[5];
    const float* wqkv   = (const float*)d_in[6];
    const float* wout   = (const float*)d_in[7];
    const float* bout   = (const float*)d_in[8];
    const float* ln2_g  = (const float*)d_in[9];
    const float* ln2_b  = (const float*)d_in[10];
    const float* w1     = (const float*)d_in[11];
    const float* b1     = (const float*)d_in[12];
    const float* w2     = (const float*)d_in[13];
    const float* b2     = (const float*)d_in[14];
    float* out = (float*)d_out;

    cudaFuncSetAttribute((const void*)mgemm_kernel<128, M_PLAIN, false>,
                         cudaFuncAttributeMaxDynamicSharedMemorySize, SMEM_BN128);
    cudaFuncSetAttribute((const void*)mgemm_kernel<128, M_PLAIN, true>,
                         cudaFuncAttributeMaxDynamicSharedMemorySize, SMEM_BN128);
    cudaFuncSetAttribute((const void*)mgemm_kernel<128, M_GEGLU, true>,
                         cudaFuncAttributeMaxDynamicSharedMemorySize, SMEM_BN128);
    cudaFuncSetAttribute((const void*)mgemm_kernel<64, M_PLAIN, false>,
                         cudaFuncAttributeMaxDynamicSharedMemorySize, SMEM_BN64);

    float *gx, *gh, *gqkv, *gsim, *gao, *gffg, *gpool, *gwt, *gws, *gvt;
    cudaGetSymbolAddress((void**)&gx,    g_x);
    cudaGetSymbolAddress((void**)&gh,    g_h);
    cudaGetSymbolAddress((void**)&gqkv,  g_qkv);
    cudaGetSymbolAddress((void**)&gsim,  g_sim);
    cudaGetSymbolAddress((void**)&gao,   g_ao);
    cudaGetSymbolAddress((void**)&gffg,  g_ffg);
    cudaGetSymbolAddress((void**)&gpool, g_pool);
    cudaGetSymbolAddress((void**)&gwt,   g_wt);
    cudaGetSymbolAddress((void**)&gws,   g_ws);
    cudaGetSymbolAddress((void**)&gvt,   g_vt);

    // ---- weight transposes (B operands as [N,K] row-major, fp32) ----
    transpose_kernel<<<dim3(16, 16, 1), dim3(32, 8)>>>(
        proj_w, D_MODEL, 0, 0, gwt + OFF_PROJ, D_MODEL, 0, 0);
    transpose_kernel<<<dim3(48, 16, 3), dim3(32, 8)>>>(
        wqkv, 3 * D_MODEL, 0, (long)D_MODEL * 3 * D_MODEL,
        gwt + OFF_QKV, D_MODEL, 0, (long)3 * D_MODEL * D_MODEL);
    transpose_kernel<<<dim3(16, 16, 3), dim3(32, 8)>>>(
        wout, D_MODEL, 0, (long)D_MODEL * D_MODEL,
        gwt + OFF_WOUT, D_MODEL, 0, (long)D_MODEL * D_MODEL);
    transpose_w1_kernel<<<dim3(128, 16, 3), dim3(32, 8)>>>(w1, gwt + OFF_W1);
    transpose_kernel<<<dim3(16, 64, 3), dim3(32, 8)>>>(
        w2, D_MODEL, 0, (long)FF * D_MODEL,
        gwt + OFF_W2, FF, 0, (long)D_MODEL * FF);

    // ---- pre-split all weights into bf16 hi/lo planes ----
    {
        // proj: N=512, K=512
        long pairs = (long)512 * 256;
        split_weights_kernel<<<(pairs + 255) / 256, 256>>>(
            gwt + OFF_PROJ, (uint32_t*)(gws + OFF_PROJ), 512, pairs);
        // qkv: N=3*1536, K=512
        pairs = (long)3 * 1536 * 256;
        split_weights_kernel<<<(pairs + 255) / 256, 256>>>(
            gwt + OFF_QKV, (uint32_t*)(gws + OFF_QKV), 512, pairs);
        // wout: N=3*512, K=512
        pairs = (long)3 * 512 * 256;
        split_weights_kernel<<<(pairs + 255) / 256, 256>>>(
            gwt + OFF_WOUT, (uint32_t*)(gws + OFF_WOUT), 512, pairs);
        // w1: N=3*4096, K=512
        pairs = (long)3 * 4096 * 256;
        split_weights_kernel<<<(pairs + 255) / 256, 256>>>(
            gwt + OFF_W1, (uint32_t*)(gws + OFF_W1), 512, pairs);
        // w2: N=3*512, K=2048
        pairs = (long)3 * 512 * 1024;
        split_weights_kernel<<<(pairs + 255) / 256, 256>>>(
            gwt + OFF_W2, (uint32_t*)(gws + OFF_W2), 2048, pairs);
    }

    // x = x @ proj_w + proj_b + pos
    launch_mg<128, M_PLAIN, true>(x, D_MODEL, 0, 0, gws + OFF_PROJ, D_MODEL, 0, 0,
                                  gx, D_MODEL, 0, 0, NROWS, D_MODEL, D_MODEL, 1,
                                  proj_b, nullptr, pos, 1.f);

    const float scale = 0.125f;

    for (int l = 0; l < NDEPTH; ++l) {
        ln_kernel<<<NROWS, 128>>>(gx, ln1_g + l * D_MODEL, ln1_b + l * D_MODEL, gh);

        // qkv = h @ Wqkv
        launch_mg<128, M_PLAIN, true>(gh, D_MODEL, 0, 0,
                                      gws + OFF_QKV + (long)l * 3 * D_MODEL * D_MODEL, D_MODEL, 0, 0,
                                      gqkv, 3 * D_MODEL, 0, 0,
                                      NROWS, 3 * D_MODEL, D_MODEL, 1,
                                      nullptr, nullptr, nullptr, 1.f);

        // V^T per (b,h): [1024,64] -> [64,1024]
        transpose_kernel<<<dim3(2, 32, NB * NHEADS), dim3(32, 8)>>>(
            gqkv + 2 * D_MODEL, 3 * D_MODEL, (long)SEQ * 3 * D_MODEL, DHEAD,
            gvt, SEQ, (long)NHEADS * DHEAD * SEQ, (long)DHEAD * SEQ);

        // sim = q @ k^T * scale
        launch_mg<128, M_PLAIN, false>(gqkv,           3 * D_MODEL, (long)SEQ * 3 * D_MODEL, DHEAD,
                                       gqkv + D_MODEL, 3 * D_MODEL, (long)SEQ * 3 * D_MODEL, DHEAD,
                                       gsim, SEQ, (long)NHEADS * SEQ * SEQ, (long)SEQ * SEQ,
                                       SEQ, SEQ, DHEAD, NB * NHEADS,
                                       nullptr, nullptr, nullptr, scale);

        sparsemax_kernel<<<NB * NHEADS * SEQ / 8, 256>>>(gsim);

        // ao = attn @ v
        launch_mg<64, M_PLAIN, false>(gsim, SEQ, (long)NHEADS * SEQ * SEQ, (long)SEQ * SEQ,
                                      gvt,  SEQ, (long)NHEADS * DHEAD * SEQ, (long)DHEAD * SEQ,
                                      gao, D_MODEL, (long)SEQ * D_MODEL, DHEAD,
                                      SEQ, DHEAD, SEQ, NB * NHEADS,
                                      nullptr, nullptr, nullptr, 1.f);

        // x = x + ao @ Wout + bout
        launch_mg<128, M_PLAIN, true>(gao, D_MODEL, 0, 0,
                                      gws + OFF_WOUT + (long)l * D_MODEL * D_MODEL, D_MODEL, 0, 0,
                                      gx, D_MODEL, 0, 0, NROWS, D_MODEL, D_MODEL, 1,
                                      bout + l * D_MODEL, gx, nullptr, 1.f);

        ln_kernel<<<NROWS, 128>>>(gx, ln2_g + l * D_MODEL, ln2_b + l * D_MODEL, gh);

        // ffg = GEGLU(h @ W1 + b1)   (fused epilogue; W1 interleaved a/g)
        launch_mg<128, M_GEGLU, true>(gh, D_MODEL, 0, 0,
                                      gws + OFF_W1 + (long)l * 2 * FF * D_MODEL, D_MODEL, 0, 0,
                                      gffg, FF, 0, 0, NROWS, 2 * FF, D_MODEL, 1,
                                      b1 + (long)l * 2 * FF, nullptr, nullptr, 1.f);

        // x = x + ffg @ W2 + b2
        launch_mg<128, M_PLAIN, true>(gffg, FF, 0, 0,
                                      gws + OFF_W2 + (long)l * D_MODEL * FF, FF, 0, 0,
                                      gx, D_MODEL, 0, 0, NROWS, D_MODEL, FF, 1,
                                      b2 + l * D_MODEL, gx, nullptr, 1.f);
    }

    pool1_kernel<<<dim3(NB, 8), 512>>>(gx, gpool);
    pool2_kernel<<<16, 256>>>(gpool, out);
}